// round 1
// baseline (speedup 1.0000x reference)
#include <cuda_runtime.h>
#include <math.h>

// Problem constants
#define BB 4
#define SS 2048
#define EE 1024
#define HH 16
#define DH 64
#define FFD 4096
#define MM (BB * SS)          // 8192 tokens
#define E3 (3 * EE)           // 3072

// ---------------------------------------------------------------------------
// Scratch buffers (device globals; allocation-free)
// ---------------------------------------------------------------------------
__device__ float g_xn[(size_t)MM * EE];     // ln1 out, reused for ln2 out
__device__ float g_qkv[(size_t)MM * E3];    // qkv projections
__device__ float g_attn[(size_t)MM * EE];   // attention output (pre O-proj)
__device__ float g_x2[(size_t)MM * EE];     // x + attn_out (post O-proj residual)
__device__ float g_fc1[(size_t)MM * FFD];   // gelu(fc1) activations

// ---------------------------------------------------------------------------
// LayerNorm: one block per token row of 1024
// ---------------------------------------------------------------------------
__global__ void __launch_bounds__(256) ln_kernel(const float* __restrict__ x,
                                                 const float* __restrict__ g,
                                                 const float* __restrict__ b,
                                                 float* __restrict__ out) {
    int row = blockIdx.x;
    const float4* xr = (const float4*)(x + (size_t)row * EE);
    float4 v = xr[threadIdx.x];
    float s  = v.x + v.y + v.z + v.w;
    float sq = v.x * v.x + v.y * v.y + v.z * v.z + v.w * v.w;
    #pragma unroll
    for (int o = 16; o; o >>= 1) {
        s  += __shfl_xor_sync(0xffffffffu, s,  o);
        sq += __shfl_xor_sync(0xffffffffu, sq, o);
    }
    __shared__ float ss[8], ssq[8];
    int w = threadIdx.x >> 5, ln = threadIdx.x & 31;
    if (ln == 0) { ss[w] = s; ssq[w] = sq; }
    __syncthreads();
    if (w == 0) {
        s  = (ln < 8) ? ss[ln]  : 0.0f;
        sq = (ln < 8) ? ssq[ln] : 0.0f;
        #pragma unroll
        for (int o = 4; o; o >>= 1) {
            s  += __shfl_xor_sync(0xffffffffu, s,  o);
            sq += __shfl_xor_sync(0xffffffffu, sq, o);
        }
        if (ln == 0) { ss[0] = s; ssq[0] = sq; }
    }
    __syncthreads();
    float mean = ss[0] * (1.0f / EE);
    float var  = ssq[0] * (1.0f / EE) - mean * mean;
    float rstd = rsqrtf(var + 1e-5f);
    int c = threadIdx.x * 4;
    float4 gg = *(const float4*)(g + c);
    float4 bb = *(const float4*)(b + c);
    float4 o4;
    o4.x = (v.x - mean) * rstd * gg.x + bb.x;
    o4.y = (v.y - mean) * rstd * gg.y + bb.y;
    o4.z = (v.z - mean) * rstd * gg.z + bb.z;
    o4.w = (v.w - mean) * rstd * gg.w + bb.w;
    ((float4*)(out + (size_t)row * EE))[threadIdx.x] = o4;
}

// ---------------------------------------------------------------------------
// SGEMM NT: C[m,n] = sum_k A[m,k]*W[n,k] (+epilogue)
//   EPI 0: + bias
//   EPI 1: + bias + residual
//   EPI 2: + bias, exact GELU
// 128x128x16 tiles, 256 threads, 8x8 per thread, double-buffered smem.
// Assumes M%128==0, N%128==0, K%16==0 (true for all calls here).
// ---------------------------------------------------------------------------
#define GBM 128
#define GBN 128
#define GBK 16

template <int EPI>
__global__ void __launch_bounds__(256) gemm_nt_kernel(
    const float* __restrict__ A, const float* __restrict__ W,
    const float* __restrict__ bias, const float* __restrict__ res,
    float* __restrict__ C, int M, int N, int K)
{
    __shared__ float As[2][GBK][GBM + 4];
    __shared__ float Bs[2][GBK][GBM + 4];

    const int tid = threadIdx.x;
    const int bm = blockIdx.y * GBM;
    const int bn = blockIdx.x * GBN;
    const int r0 = (tid >> 4) << 3;    // 0..120
    const int c0 = (tid & 15) << 3;    // 0..120
    const int lrow = tid >> 2;         // 0..63
    const int lk = (tid & 3) << 2;     // 0,4,8,12

    const float* Ap = A + (size_t)(bm + lrow) * K + lk;
    const float* Wp = W + (size_t)(bn + lrow) * K + lk;
    const size_t rstride = (size_t)64 * K;

    float acc[8][8];
    #pragma unroll
    for (int i = 0; i < 8; i++)
        #pragma unroll
        for (int j = 0; j < 8; j++) acc[i][j] = 0.0f;

    float4 pa0, pa1, pb0, pb1;
    // prefetch tile 0
    pa0 = *(const float4*)Ap;
    pa1 = *(const float4*)(Ap + rstride);
    pb0 = *(const float4*)Wp;
    pb1 = *(const float4*)(Wp + rstride);
    {
        float va[4] = {pa0.x, pa0.y, pa0.z, pa0.w};
        float vA[4] = {pa1.x, pa1.y, pa1.z, pa1.w};
        float vb[4] = {pb0.x, pb0.y, pb0.z, pb0.w};
        float vB[4] = {pb1.x, pb1.y, pb1.z, pb1.w};
        #pragma unroll
        for (int j = 0; j < 4; j++) {
            As[0][lk + j][lrow]      = va[j];
            As[0][lk + j][lrow + 64] = vA[j];
            Bs[0][lk + j][lrow]      = vb[j];
            Bs[0][lk + j][lrow + 64] = vB[j];
        }
    }
    __syncthreads();

    const int nk = K / GBK;
    for (int kt = 0; kt < nk; ++kt) {
        const int buf = kt & 1;
        const bool pf = (kt + 1 < nk);
        if (pf) {
            const float* ap = Ap + (size_t)(kt + 1) * GBK;
            const float* wp = Wp + (size_t)(kt + 1) * GBK;
            pa0 = *(const float4*)ap;
            pa1 = *(const float4*)(ap + rstride);
            pb0 = *(const float4*)wp;
            pb1 = *(const float4*)(wp + rstride);
        }
        #pragma unroll
        for (int kk = 0; kk < GBK; ++kk) {
            float af[8], bf[8];
            *(float4*)(af)     = *(const float4*)&As[buf][kk][r0];
            *(float4*)(af + 4) = *(const float4*)&As[buf][kk][r0 + 4];
            *(float4*)(bf)     = *(const float4*)&Bs[buf][kk][c0];
            *(float4*)(bf + 4) = *(const float4*)&Bs[buf][kk][c0 + 4];
            #pragma unroll
            for (int i = 0; i < 8; i++)
                #pragma unroll
                for (int j = 0; j < 8; j++)
                    acc[i][j] = fmaf(af[i], bf[j], acc[i][j]);
        }
        if (pf) {
            const int nb = buf ^ 1;
            float va[4] = {pa0.x, pa0.y, pa0.z, pa0.w};
            float vA[4] = {pa1.x, pa1.y, pa1.z, pa1.w};
            float vb[4] = {pb0.x, pb0.y, pb0.z, pb0.w};
            float vB[4] = {pb1.x, pb1.y, pb1.z, pb1.w};
            #pragma unroll
            for (int j = 0; j < 4; j++) {
                As[nb][lk + j][lrow]      = va[j];
                As[nb][lk + j][lrow + 64] = vA[j];
                Bs[nb][lk + j][lrow]      = vb[j];
                Bs[nb][lk + j][lrow + 64] = vB[j];
            }
        }
        __syncthreads();
    }

    // epilogue
    float bfrag[8];
    *(float4*)(bfrag)     = *(const float4*)(bias + bn + c0);
    *(float4*)(bfrag + 4) = *(const float4*)(bias + bn + c0 + 4);
    #pragma unroll
    for (int i = 0; i < 8; i++) {
        const int m = bm + r0 + i;
        float o[8];
        #pragma unroll
        for (int j = 0; j < 8; j++) {
            float v = acc[i][j] + bfrag[j];
            if (EPI == 2) v = 0.5f * v * (1.0f + erff(v * 0.70710678118654752f));
            o[j] = v;
        }
        if (EPI == 1) {
            const float* rp = res + (size_t)m * N + bn + c0;
            float4 r04 = *(const float4*)rp;
            float4 r14 = *(const float4*)(rp + 4);
            o[0] += r04.x; o[1] += r04.y; o[2] += r04.z; o[3] += r04.w;
            o[4] += r14.x; o[5] += r14.y; o[6] += r14.z; o[7] += r14.w;
        }
        float* cp = C + (size_t)m * N + bn + c0;
        *(float4*)cp       = make_float4(o[0], o[1], o[2], o[3]);
        *(float4*)(cp + 4) = make_float4(o[4], o[5], o[6], o[7]);
    }
}

// ---------------------------------------------------------------------------
// Flash attention with custom mask:
//   masked if (j > i) || (j % TD == TD-1)
// grid = (S/64, B*H); 64-query x 32-key tiles; online softmax in fp32.
// ---------------------------------------------------------------------------
__global__ void __launch_bounds__(256) attn_kernel(const float* __restrict__ qkv,
                                                   const int* __restrict__ tdp,
                                                   float* __restrict__ out) {
    __shared__ float qs[64][65];
    __shared__ float ks[32][65];
    __shared__ float vs[32][65];
    __shared__ float ps[64][33];

    const int qb = blockIdx.x;          // query tile (64 rows)
    const int bh = blockIdx.y;          // b*H + h
    const int bb = bh >> 4;
    const int h  = bh & 15;
    const int TD = tdp[0];
    const int tid = threadIdx.x;
    const int tx = tid & 15, ty = tid >> 4;
    const int r0 = ty * 4;              // 4 query rows per thread
    const int kc0 = tx * 2;             // 2 key cols (scores phase)
    const int dc0 = tx * 4;             // 4 head-dims (PV phase)

    const size_t base = (size_t)bb * SS * E3 + (size_t)h * DH;

    // load Q tile
    for (int idx = tid; idx < 64 * 64; idx += 256) {
        int r = idx >> 6, d = idx & 63;
        qs[r][d] = qkv[base + (size_t)(qb * 64 + r) * E3 + d];
    }

    float m[4], l[4], acc[4][4];
    #pragma unroll
    for (int i = 0; i < 4; i++) {
        m[i] = -1e30f; l[i] = 0.0f;
        #pragma unroll
        for (int j = 0; j < 4; j++) acc[i][j] = 0.0f;
    }

    const int nkt = 2 * qb + 2;   // 32-key tiles up to & including diagonal
    for (int kb = 0; kb < nkt; ++kb) {
        __syncthreads();   // prev PV done (and Q ready on first iter)
        for (int idx = tid; idx < 32 * 64; idx += 256) {
            int r = idx >> 6, d = idx & 63;
            size_t toff = base + (size_t)(kb * 32 + r) * E3 + d;
            ks[r][d] = qkv[toff + EE];
            vs[r][d] = qkv[toff + 2 * EE];
        }
        __syncthreads();

        // scores: s[4 rows][2 key cols]
        float s[4][2] = {{0.f,0.f},{0.f,0.f},{0.f,0.f},{0.f,0.f}};
        #pragma unroll 8
        for (int d = 0; d < 64; ++d) {
            float k0 = ks[kc0][d], k1 = ks[kc0 + 1][d];
            #pragma unroll
            for (int i = 0; i < 4; i++) {
                float qv = qs[r0 + i][d];
                s[i][0] = fmaf(qv, k0, s[i][0]);
                s[i][1] = fmaf(qv, k1, s[i][1]);
            }
        }

        const int ig0 = qb * 64 + r0;
        const int jg0 = kb * 32 + kc0;
        float rm[4];
        #pragma unroll
        for (int i = 0; i < 4; i++) {
            #pragma unroll
            for (int j = 0; j < 2; j++) {
                int jg = jg0 + j;
                bool masked = (jg > ig0 + i) || ((jg % TD) == TD - 1);
                s[i][j] = masked ? -1e30f : s[i][j] * 0.125f;
            }
            rm[i] = fmaxf(s[i][0], s[i][1]);
        }
        // row-max across 16 lanes (same ty)
        #pragma unroll
        for (int o = 1; o < 16; o <<= 1)
            #pragma unroll
            for (int i = 0; i < 4; i++)
                rm[i] = fmaxf(rm[i], __shfl_xor_sync(0xffffffffu, rm[i], o));

        float alpha[4], rs[4];
        #pragma unroll
        for (int i = 0; i < 4; i++) {
            float mn = fmaxf(m[i], rm[i]);
            alpha[i] = expf(m[i] - mn);
            m[i] = mn;
            float p0 = expf(s[i][0] - mn);
            float p1 = expf(s[i][1] - mn);
            ps[r0 + i][kc0]     = p0;
            ps[r0 + i][kc0 + 1] = p1;
            rs[i] = p0 + p1;
        }
        #pragma unroll
        for (int o = 1; o < 16; o <<= 1)
            #pragma unroll
            for (int i = 0; i < 4; i++)
                rs[i] += __shfl_xor_sync(0xffffffffu, rs[i], o);
        #pragma unroll
        for (int i = 0; i < 4; i++) {
            l[i] = l[i] * alpha[i] + rs[i];
            #pragma unroll
            for (int j = 0; j < 4; j++) acc[i][j] *= alpha[i];
        }
        __syncthreads();  // ps visible, vs loaded

        // PV: acc[4 rows][4 dims]
        #pragma unroll 8
        for (int k = 0; k < 32; ++k) {
            float v0 = vs[k][dc0], v1 = vs[k][dc0 + 1];
            float v2 = vs[k][dc0 + 2], v3 = vs[k][dc0 + 3];
            #pragma unroll
            for (int i = 0; i < 4; i++) {
                float p = ps[r0 + i][k];
                acc[i][0] = fmaf(p, v0, acc[i][0]);
                acc[i][1] = fmaf(p, v1, acc[i][1]);
                acc[i][2] = fmaf(p, v2, acc[i][2]);
                acc[i][3] = fmaf(p, v3, acc[i][3]);
            }
        }
    }

    #pragma unroll
    for (int i = 0; i < 4; i++) {
        float inv = 1.0f / l[i];
        size_t orow = ((size_t)bb * SS + qb * 64 + r0 + i) * EE + h * DH + dc0;
        #pragma unroll
        for (int j = 0; j < 4; j++)
            out[orow + j] = acc[i][j] * inv;
    }
}

// ---------------------------------------------------------------------------
// Launch
// ---------------------------------------------------------------------------
extern "C" void kernel_launch(void* const* d_in, const int* in_sizes, int n_in,
                              void* d_out, int out_size) {
    const float* x      = (const float*)d_in[0];
    const int*   td     = (const int*)d_in[1];
    const float* ln1_g  = (const float*)d_in[2];
    const float* ln1_b  = (const float*)d_in[3];
    const float* ln2_g  = (const float*)d_in[4];
    const float* ln2_b  = (const float*)d_in[5];
    const float* w_qkv  = (const float*)d_in[6];
    const float* b_qkv  = (const float*)d_in[7];
    const float* w_o    = (const float*)d_in[8];
    const float* b_o    = (const float*)d_in[9];
    const float* w_fc1  = (const float*)d_in[10];
    const float* b_fc1  = (const float*)d_in[11];
    const float* w_fc2  = (const float*)d_in[12];
    const float* b_fc2  = (const float*)d_in[13];
    float* out = (float*)d_out;

    float *xn, *qkvb, *attnb, *x2, *fc1b;
    cudaGetSymbolAddress((void**)&xn,    g_xn);
    cudaGetSymbolAddress((void**)&qkvb,  g_qkv);
    cudaGetSymbolAddress((void**)&attnb, g_attn);
    cudaGetSymbolAddress((void**)&x2,    g_x2);
    cudaGetSymbolAddress((void**)&fc1b,  g_fc1);

    // 1. LN1
    ln_kernel<<<MM, 256>>>(x, ln1_g, ln1_b, xn);
    // 2. QKV projection: [8192,3072] = xn @ w_qkv^T + b_qkv
    gemm_nt_kernel<0><<<dim3(E3 / GBN, MM / GBM), 256>>>(xn, w_qkv, b_qkv, nullptr,
                                                         qkvb, MM, E3, EE);
    // 3. Attention
    attn_kernel<<<dim3(SS / 64, BB * HH), 256>>>(qkvb, td, attnb);
    // 4. O projection + residual: x2 = x + attn @ w_o^T + b_o
    gemm_nt_kernel<1><<<dim3(EE / GBN, MM / GBM), 256>>>(attnb, w_o, b_o, x,
                                                         x2, MM, EE, EE);
    // 5. LN2
    ln_kernel<<<MM, 256>>>(x2, ln2_g, ln2_b, xn);
    // 6. FC1 + GELU
    gemm_nt_kernel<2><<<dim3(FFD / GBN, MM / GBM), 256>>>(xn, w_fc1, b_fc1, nullptr,
                                                          fc1b, MM, FFD, EE);
    // 7. FC2 + residual -> out
    gemm_nt_kernel<1><<<dim3(EE / GBN, MM / GBM), 256>>>(fc1b, w_fc2, b_fc2, x2,
                                                         out, MM, EE, FFD);
}

// round 3
// speedup vs baseline: 2.0512x; 2.0512x over previous
#include <cuda_runtime.h>
#include <math.h>
#include <stdint.h>

// Problem constants
#define BB 4
#define SS 2048
#define EE 1024
#define HH 16
#define DH 64
#define FFD 4096
#define MM (BB * SS)          // 8192 tokens
#define E3 (3 * EE)           // 3072

// ---------------------------------------------------------------------------
// Scratch buffers (device globals; allocation-free)
// ---------------------------------------------------------------------------
__device__ __align__(128) float g_xn[(size_t)MM * EE];
__device__ __align__(128) float g_qkv[(size_t)MM * E3];
__device__ __align__(128) float g_attn[(size_t)MM * EE];
__device__ __align__(128) float g_x2[(size_t)MM * EE];
__device__ __align__(128) float g_fc1[(size_t)MM * FFD];
// tf32-rounded weights: qkv(3M) | o(1M) | fc1(4M) | fc2(4M)
__device__ __align__(128) float g_wc[(size_t)12 * 1024 * 1024];

// ---------------------------------------------------------------------------
// Helpers
// ---------------------------------------------------------------------------
__device__ __forceinline__ float rtf32(float x) {
    uint32_t u;
    asm("cvt.rna.tf32.f32 %0, %1;" : "=r"(u) : "f"(x));
    return __uint_as_float(u);
}
__device__ __forceinline__ uint32_t smem_u32(const void* p) {
    uint32_t a;
    asm("{ .reg .u64 t; cvta.to.shared.u64 t, %1; cvt.u32.u64 %0, t; }"
        : "=r"(a) : "l"(p));
    return a;
}
__device__ __forceinline__ void cp16(uint32_t s, const void* g) {
    asm volatile("cp.async.cg.shared.global [%0], [%1], 16;" :: "r"(s), "l"(g));
}
#define CP_COMMIT asm volatile("cp.async.commit_group;" ::: "memory")
#define CP_WAIT1  asm volatile("cp.async.wait_group 1;" ::: "memory")

__device__ __forceinline__ void mma8(float c[4], const uint32_t a[4],
                                     uint32_t b0, uint32_t b1) {
    asm volatile(
        "mma.sync.aligned.m16n8k8.row.col.f32.tf32.tf32.f32 "
        "{%0,%1,%2,%3}, {%4,%5,%6,%7}, {%8,%9}, {%0,%1,%2,%3};"
        : "+f"(c[0]), "+f"(c[1]), "+f"(c[2]), "+f"(c[3])
        : "r"(a[0]), "r"(a[1]), "r"(a[2]), "r"(a[3]), "r"(b0), "r"(b1));
}

// ---------------------------------------------------------------------------
// Weight round-to-tf32 pass
// ---------------------------------------------------------------------------
__global__ void __launch_bounds__(256) round_kernel(const float* __restrict__ in,
                                                    float* __restrict__ out, int n) {
    int i = (blockIdx.x * 256 + threadIdx.x) * 4;
    if (i < n) {
        float4 v = *(const float4*)(in + i);
        v.x = rtf32(v.x); v.y = rtf32(v.y); v.z = rtf32(v.z); v.w = rtf32(v.w);
        *(float4*)(out + i) = v;
    }
}

// ---------------------------------------------------------------------------
// TF32 mma.sync GEMM NT: C[m,n] = sum_k A[m,k]*W[n,k] (+epilogue)
//   EPI 0: + bias
//   EPI 1: + bias + residual
//   EPI 2: + bias, exact GELU, round output to tf32
// CTA tile 128x128x32, 8 warps (4Mx2N), warp tile 32x64, double-buffer cp.async.
// A,W must be tf32-rounded already. Requires M%128==0, N%128==0, K%32==0.
// ---------------------------------------------------------------------------
#define BM 128
#define BN 128
#define BKF 32
#define SROW 36                      // padded smem row stride (floats)
#define STG_FLOATS (2 * BM * SROW)   // As+Bs per stage = 9216 floats

template <int EPI>
__global__ void __launch_bounds__(256, 2) gemm_mma(
    const float* __restrict__ A, const float* __restrict__ W,
    const float* __restrict__ bias, const float* __restrict__ res,
    float* __restrict__ C, int M, int N, int K)
{
    extern __shared__ float sm[];
    const int tid = threadIdx.x;
    const int bm = blockIdx.y * BM;
    const int bn = blockIdx.x * BN;
    const uint32_t sbase = smem_u32(sm);

    const int w = tid >> 5, lane = tid & 31;
    const int g = lane >> 2, t = lane & 3;
    const int wm = (w & 3) * 32;       // warp M offset in tile
    const int wn = (w >> 2) * 64;      // warp N offset in tile

    // global load mapping: 4 chunks of A + 4 of B per thread
    const int r_ld = tid >> 1;                 // 0..127 (two chunks per row pair)
    const float* Ag = A + (size_t)bm * K;
    const float* Wg = W + (size_t)bn * K;

    float acc[2][8][4];
    #pragma unroll
    for (int mi = 0; mi < 2; mi++)
        #pragma unroll
        for (int ni = 0; ni < 8; ni++)
            #pragma unroll
            for (int j = 0; j < 4; j++) acc[mi][ni][j] = 0.0f;

    auto load_tile = [&](int stg, int kt) {
        const uint32_t dA = sbase + stg * (STG_FLOATS * 4);
        const uint32_t dB = dA + BM * SROW * 4;
        const int kofs = kt * BKF;
        #pragma unroll
        for (int i = 0; i < 4; i++) {
            int chunk = tid + i * 256;          // 0..1023
            int r = chunk >> 3, c = chunk & 7;  // row 0..127, 16B chunk 0..7
            cp16(dA + (r * SROW + c * 4) * 4, Ag + (size_t)r * K + kofs + c * 4);
            cp16(dB + (r * SROW + c * 4) * 4, Wg + (size_t)r * K + kofs + c * 4);
        }
    };

    const int nk = K / BKF;
    load_tile(0, 0);
    CP_COMMIT;

    for (int kt = 0; kt < nk; kt++) {
        const int buf = kt & 1;
        if (kt + 1 < nk) load_tile(buf ^ 1, kt + 1);
        CP_COMMIT;
        CP_WAIT1;
        __syncthreads();

        const float* As = sm + buf * STG_FLOATS;
        const float* Bs = As + BM * SROW;
        const float* aB = As + (wm + g) * SROW + t;
        const float* bB = Bs + (wn + g) * SROW + t;

        #pragma unroll
        for (int ks = 0; ks < 4; ks++) {
            const int k0 = ks * 8;
            uint32_t af[2][4];
            #pragma unroll
            for (int mi = 0; mi < 2; mi++) {
                const float* p = aB + mi * 16 * SROW + k0;
                af[mi][0] = __float_as_uint(p[0]);
                af[mi][1] = __float_as_uint(p[8 * SROW]);
                af[mi][2] = __float_as_uint(p[4]);
                af[mi][3] = __float_as_uint(p[8 * SROW + 4]);
            }
            #pragma unroll
            for (int ni = 0; ni < 8; ni++) {
                const float* p = bB + ni * 8 * SROW + k0;
                uint32_t b0 = __float_as_uint(p[0]);
                uint32_t b1 = __float_as_uint(p[4]);
                mma8(acc[0][ni], af[0], b0, b1);
                mma8(acc[1][ni], af[1], b0, b1);
            }
        }
        __syncthreads();
    }

    // epilogue
    float bb[8][2];
    #pragma unroll
    for (int ni = 0; ni < 8; ni++) {
        int col = bn + wn + ni * 8 + t * 2;
        bb[ni][0] = __ldg(bias + col);
        bb[ni][1] = __ldg(bias + col + 1);
    }
    #pragma unroll
    for (int mi = 0; mi < 2; mi++) {
        #pragma unroll
        for (int h = 0; h < 2; h++) {
            const int row = bm + wm + mi * 16 + g + h * 8;
            #pragma unroll
            for (int ni = 0; ni < 8; ni++) {
                const int col = bn + wn + ni * 8 + t * 2;
                float o0 = acc[mi][ni][h * 2 + 0] + bb[ni][0];
                float o1 = acc[mi][ni][h * 2 + 1] + bb[ni][1];
                if (EPI == 2) {
                    o0 = 0.5f * o0 * (1.0f + erff(o0 * 0.70710678118654752f));
                    o1 = 0.5f * o1 * (1.0f + erff(o1 * 0.70710678118654752f));
                    o0 = rtf32(o0); o1 = rtf32(o1);
                }
                if (EPI == 1) {
                    const float2 rv = *(const float2*)(res + (size_t)row * N + col);
                    o0 += rv.x; o1 += rv.y;
                }
                *(float2*)(C + (size_t)row * N + col) = make_float2(o0, o1);
            }
        }
    }
}

// ---------------------------------------------------------------------------
// LayerNorm: one block per token row of 1024; output rounded to tf32
// (output feeds GEMM A-operands only)
// ---------------------------------------------------------------------------
__global__ void __launch_bounds__(256) ln_kernel(const float* __restrict__ x,
                                                 const float* __restrict__ g,
                                                 const float* __restrict__ b,
                                                 float* __restrict__ out) {
    int row = blockIdx.x;
    const float4* xr = (const float4*)(x + (size_t)row * EE);
    float4 v = xr[threadIdx.x];
    float s  = v.x + v.y + v.z + v.w;
    float sq = v.x * v.x + v.y * v.y + v.z * v.z + v.w * v.w;
    #pragma unroll
    for (int o = 16; o; o >>= 1) {
        s  += __shfl_xor_sync(0xffffffffu, s,  o);
        sq += __shfl_xor_sync(0xffffffffu, sq, o);
    }
    __shared__ float ss[8], ssq[8];
    int w = threadIdx.x >> 5, ln = threadIdx.x & 31;
    if (ln == 0) { ss[w] = s; ssq[w] = sq; }
    __syncthreads();
    if (w == 0) {
        s  = (ln < 8) ? ss[ln]  : 0.0f;
        sq = (ln < 8) ? ssq[ln] : 0.0f;
        #pragma unroll
        for (int o = 4; o; o >>= 1) {
            s  += __shfl_xor_sync(0xffffffffu, s,  o);
            sq += __shfl_xor_sync(0xffffffffu, sq, o);
        }
        if (ln == 0) { ss[0] = s; ssq[0] = sq; }
    }
    __syncthreads();
    float mean = ss[0] * (1.0f / EE);
    float var  = ssq[0] * (1.0f / EE) - mean * mean;
    float rstd = rsqrtf(var + 1e-5f);
    int c = threadIdx.x * 4;
    float4 gg = *(const float4*)(g + c);
    float4 bb = *(const float4*)(b + c);
    float4 o4;
    o4.x = rtf32((v.x - mean) * rstd * gg.x + bb.x);
    o4.y = rtf32((v.y - mean) * rstd * gg.y + bb.y);
    o4.z = rtf32((v.z - mean) * rstd * gg.z + bb.z);
    o4.w = rtf32((v.w - mean) * rstd * gg.w + bb.w);
    ((float4*)(out + (size_t)row * EE))[threadIdx.x] = o4;
}

// ---------------------------------------------------------------------------
// Flash attention with custom mask: masked if (j > i) || (j % TD == TD-1)
// Output rounded to tf32 (feeds O-projection GEMM only).
// ---------------------------------------------------------------------------
__global__ void __launch_bounds__(256) attn_kernel(const float* __restrict__ qkv,
                                                   const int* __restrict__ tdp,
                                                   float* __restrict__ out) {
    __shared__ float qs[64][65];
    __shared__ float ks[32][65];
    __shared__ float vs[32][65];
    __shared__ float ps[64][33];

    const int qb = blockIdx.x;
    const int bh = blockIdx.y;
    const int bb = bh >> 4;
    const int h  = bh & 15;
    const int TD = tdp[0];
    const int tid = threadIdx.x;
    const int tx = tid & 15, ty = tid >> 4;
    const int r0 = ty * 4;
    const int kc0 = tx * 2;
    const int dc0 = tx * 4;

    const size_t base = (size_t)bb * SS * E3 + (size_t)h * DH;

    for (int idx = tid; idx < 64 * 64; idx += 256) {
        int r = idx >> 6, d = idx & 63;
        qs[r][d] = qkv[base + (size_t)(qb * 64 + r) * E3 + d];
    }

    float m[4], l[4], acc[4][4];
    #pragma unroll
    for (int i = 0; i < 4; i++) {
        m[i] = -1e30f; l[i] = 0.0f;
        #pragma unroll
        for (int j = 0; j < 4; j++) acc[i][j] = 0.0f;
    }

    const int nkt = 2 * qb + 2;
    for (int kb = 0; kb < nkt; ++kb) {
        __syncthreads();
        for (int idx = tid; idx < 32 * 64; idx += 256) {
            int r = idx >> 6, d = idx & 63;
            size_t toff = base + (size_t)(kb * 32 + r) * E3 + d;
            ks[r][d] = qkv[toff + EE];
            vs[r][d] = qkv[toff + 2 * EE];
        }
        __syncthreads();

        float s[4][2] = {{0.f,0.f},{0.f,0.f},{0.f,0.f},{0.f,0.f}};
        #pragma unroll 8
        for (int d = 0; d < 64; ++d) {
            float k0 = ks[kc0][d], k1 = ks[kc0 + 1][d];
            #pragma unroll
            for (int i = 0; i < 4; i++) {
                float qv = qs[r0 + i][d];
                s[i][0] = fmaf(qv, k0, s[i][0]);
                s[i][1] = fmaf(qv, k1, s[i][1]);
            }
        }

        const int ig0 = qb * 64 + r0;
        const int jg0 = kb * 32 + kc0;
        float rm[4];
        #pragma unroll
        for (int i = 0; i < 4; i++) {
            #pragma unroll
            for (int j = 0; j < 2; j++) {
                int jg = jg0 + j;
                bool masked = (jg > ig0 + i) || ((jg % TD) == TD - 1);
                s[i][j] = masked ? -1e30f : s[i][j] * 0.125f;
            }
            rm[i] = fmaxf(s[i][0], s[i][1]);
        }
        #pragma unroll
        for (int o = 1; o < 16; o <<= 1)
            #pragma unroll
            for (int i = 0; i < 4; i++)
                rm[i] = fmaxf(rm[i], __shfl_xor_sync(0xffffffffu, rm[i], o));

        float alpha[4], rs[4];
        #pragma unroll
        for (int i = 0; i < 4; i++) {
            float mn = fmaxf(m[i], rm[i]);
            alpha[i] = expf(m[i] - mn);
            m[i] = mn;
            float p0 = expf(s[i][0] - mn);
            float p1 = expf(s[i][1] - mn);
            ps[r0 + i][kc0]     = p0;
            ps[r0 + i][kc0 + 1] = p1;
            rs[i] = p0 + p1;
        }
        #pragma unroll
        for (int o = 1; o < 16; o <<= 1)
            #pragma unroll
            for (int i = 0; i < 4; i++)
                rs[i] += __shfl_xor_sync(0xffffffffu, rs[i], o);
        #pragma unroll
        for (int i = 0; i < 4; i++) {
            l[i] = l[i] * alpha[i] + rs[i];
            #pragma unroll
            for (int j = 0; j < 4; j++) acc[i][j] *= alpha[i];
        }
        __syncthreads();

        #pragma unroll 8
        for (int k = 0; k < 32; ++k) {
            float v0 = vs[k][dc0], v1 = vs[k][dc0 + 1];
            float v2 = vs[k][dc0 + 2], v3 = vs[k][dc0 + 3];
            #pragma unroll
            for (int i = 0; i < 4; i++) {
                float p = ps[r0 + i][k];
                acc[i][0] = fmaf(p, v0, acc[i][0]);
                acc[i][1] = fmaf(p, v1, acc[i][1]);
                acc[i][2] = fmaf(p, v2, acc[i][2]);
                acc[i][3] = fmaf(p, v3, acc[i][3]);
            }
        }
    }

    #pragma unroll
    for (int i = 0; i < 4; i++) {
        float inv = 1.0f / l[i];
        size_t orow = ((size_t)bb * SS + qb * 64 + r0 + i) * EE + h * DH + dc0;
        #pragma unroll
        for (int j = 0; j < 4; j++)
            out[orow + j] = rtf32(acc[i][j] * inv);
    }
}

// ---------------------------------------------------------------------------
// Launch
// ---------------------------------------------------------------------------
extern "C" void kernel_launch(void* const* d_in, const int* in_sizes, int n_in,
                              void* d_out, int out_size) {
    const float* x      = (const float*)d_in[0];
    const int*   td     = (const int*)d_in[1];
    const float* ln1_g  = (const float*)d_in[2];
    const float* ln1_b  = (const float*)d_in[3];
    const float* ln2_g  = (const float*)d_in[4];
    const float* ln2_b  = (const float*)d_in[5];
    const float* w_qkv  = (const float*)d_in[6];
    const float* b_qkv  = (const float*)d_in[7];
    const float* w_o    = (const float*)d_in[8];
    const float* b_o    = (const float*)d_in[9];
    const float* w_fc1  = (const float*)d_in[10];
    const float* b_fc1  = (const float*)d_in[11];
    const float* w_fc2  = (const float*)d_in[12];
    const float* b_fc2  = (const float*)d_in[13];
    float* out = (float*)d_out;

    float *xn, *qkvb, *attnb, *x2, *fc1b, *wc;
    cudaGetSymbolAddress((void**)&xn,    g_xn);
    cudaGetSymbolAddress((void**)&qkvb,  g_qkv);
    cudaGetSymbolAddress((void**)&attnb, g_attn);
    cudaGetSymbolAddress((void**)&x2,    g_x2);
    cudaGetSymbolAddress((void**)&fc1b,  g_fc1);
    cudaGetSymbolAddress((void**)&wc,    g_wc);

    float* wc_qkv = wc;                                  // 3M floats
    float* wc_o   = wc + (size_t)3 * 1024 * 1024;        // 1M
    float* wc_fc1 = wc + (size_t)4 * 1024 * 1024;        // 4M
    float* wc_fc2 = wc + (size_t)8 * 1024 * 1024;        // 4M

    const int dsm = 2 * STG_FLOATS * 4;  // 73728 bytes
    cudaFuncSetAttribute(gemm_mma<0>, cudaFuncAttributeMaxDynamicSharedMemorySize, dsm);
    cudaFuncSetAttribute(gemm_mma<1>, cudaFuncAttributeMaxDynamicSharedMemorySize, dsm);
    cudaFuncSetAttribute(gemm_mma<2>, cudaFuncAttributeMaxDynamicSharedMemorySize, dsm);

    // 0. Round weights to tf32 once per call
    round_kernel<<<(E3 * EE / 4 + 255) / 256, 256>>>(w_qkv, wc_qkv, E3 * EE);
    round_kernel<<<(EE * EE / 4 + 255) / 256, 256>>>(w_o,   wc_o,   EE * EE);
    round_kernel<<<(FFD * EE / 4 + 255) / 256, 256>>>(w_fc1, wc_fc1, FFD * EE);
    round_kernel<<<(EE * FFD / 4 + 255) / 256, 256>>>(w_fc2, wc_fc2, EE * FFD);

    // 1. LN1 (tf32-rounded output)
    ln_kernel<<<MM, 256>>>(x, ln1_g, ln1_b, xn);
    // 2. QKV projection
    gemm_mma<0><<<dim3(E3 / BN, MM / BM), 256, dsm>>>(xn, wc_qkv, b_qkv, nullptr,
                                                      qkvb, MM, E3, EE);
    // 3. Attention
    attn_kernel<<<dim3(SS / 64, BB * HH), 256>>>(qkvb, td, attnb);
    // 4. O projection + residual
    gemm_mma<1><<<dim3(EE / BN, MM / BM), 256, dsm>>>(attnb, wc_o, b_o, x,
                                                      x2, MM, EE, EE);
    // 5. LN2
    ln_kernel<<<MM, 256>>>(x2, ln2_g, ln2_b, xn);
    // 6. FC1 + GELU (tf32-rounded output)
    gemm_mma<2><<<dim3(FFD / BN, MM / BM), 256, dsm>>>(xn, wc_fc1, b_fc1, nullptr,
                                                       fc1b, MM, FFD, EE);
    // 7. FC2 + residual -> out
    gemm_mma<1><<<dim3(EE / BN, MM / BM), 256, dsm>>>(fc1b, wc_fc2, b_fc2, x2,
                                                      out, MM, EE, FFD);
}

// round 4
// speedup vs baseline: 3.0424x; 1.4832x over previous
#include <cuda_runtime.h>
#include <math.h>
#include <stdint.h>

// Problem constants
#define BB 4
#define SS 2048
#define EE 1024
#define HH 16
#define DH 64
#define FFD 4096
#define MM (BB * SS)          // 8192 tokens
#define E3 (3 * EE)           // 3072

// ---------------------------------------------------------------------------
// Scratch buffers (device globals; allocation-free)
// ---------------------------------------------------------------------------
__device__ __align__(128) float g_xn[(size_t)MM * EE];
__device__ __align__(128) float g_qkv[(size_t)MM * E3];
__device__ __align__(128) float g_attn[(size_t)MM * EE];
__device__ __align__(128) float g_x2[(size_t)MM * EE];
__device__ __align__(128) float g_fc1[(size_t)MM * FFD];
// tf32-rounded weights: qkv(3M) | o(1M) | fc1(4M) | fc2(4M)
__device__ __align__(128) float g_wc[(size_t)12 * 1024 * 1024];

// ---------------------------------------------------------------------------
// Helpers
// ---------------------------------------------------------------------------
__device__ __forceinline__ float rtf32(float x) {
    uint32_t u;
    asm("cvt.rna.tf32.f32 %0, %1;" : "=r"(u) : "f"(x));
    return __uint_as_float(u);
}
__device__ __forceinline__ uint32_t smem_u32(const void* p) {
    uint32_t a;
    asm("{ .reg .u64 t; cvta.to.shared.u64 t, %1; cvt.u32.u64 %0, t; }"
        : "=r"(a) : "l"(p));
    return a;
}
__device__ __forceinline__ void cp16(uint32_t s, const void* g) {
    asm volatile("cp.async.cg.shared.global [%0], [%1], 16;" :: "r"(s), "l"(g));
}
#define CP_COMMIT asm volatile("cp.async.commit_group;" ::: "memory")
#define CP_WAIT1  asm volatile("cp.async.wait_group 1;" ::: "memory")

__device__ __forceinline__ void mma8(float c[4], const uint32_t a[4],
                                     uint32_t b0, uint32_t b1) {
    asm volatile(
        "mma.sync.aligned.m16n8k8.row.col.f32.tf32.tf32.f32 "
        "{%0,%1,%2,%3}, {%4,%5,%6,%7}, {%8,%9}, {%0,%1,%2,%3};"
        : "+f"(c[0]), "+f"(c[1]), "+f"(c[2]), "+f"(c[3])
        : "r"(a[0]), "r"(a[1]), "r"(a[2]), "r"(a[3]), "r"(b0), "r"(b1));
}

// ---------------------------------------------------------------------------
// Weight round-to-tf32 pass
// ---------------------------------------------------------------------------
__global__ void __launch_bounds__(256) round_kernel(const float* __restrict__ in,
                                                    float* __restrict__ out, int n) {
    int i = (blockIdx.x * 256 + threadIdx.x) * 4;
    if (i < n) {
        float4 v = *(const float4*)(in + i);
        v.x = rtf32(v.x); v.y = rtf32(v.y); v.z = rtf32(v.z); v.w = rtf32(v.w);
        *(float4*)(out + i) = v;
    }
}

// ---------------------------------------------------------------------------
// TF32 mma.sync GEMM NT: C[m,n] = sum_k A[m,k]*W[n,k] (+epilogue)
//   EPI 0: + bias, round output to tf32 (QKV: feeds attention mma)
//   EPI 1: + bias + residual (fp32)
//   EPI 2: + bias, exact GELU, round output to tf32
// ---------------------------------------------------------------------------
#define BM 128
#define BN 128
#define BKF 32
#define SROW 36                      // padded smem row stride (floats)
#define STG_FLOATS (2 * BM * SROW)   // As+Bs per stage = 9216 floats

template <int EPI>
__global__ void __launch_bounds__(256, 2) gemm_mma(
    const float* __restrict__ A, const float* __restrict__ W,
    const float* __restrict__ bias, const float* __restrict__ res,
    float* __restrict__ C, int M, int N, int K)
{
    extern __shared__ float sm[];
    const int tid = threadIdx.x;
    const int bm = blockIdx.y * BM;
    const int bn = blockIdx.x * BN;
    const uint32_t sbase = smem_u32(sm);

    const int w = tid >> 5, lane = tid & 31;
    const int g = lane >> 2, t = lane & 3;
    const int wm = (w & 3) * 32;
    const int wn = (w >> 2) * 64;

    const float* Ag = A + (size_t)bm * K;
    const float* Wg = W + (size_t)bn * K;

    float acc[2][8][4];
    #pragma unroll
    for (int mi = 0; mi < 2; mi++)
        #pragma unroll
        for (int ni = 0; ni < 8; ni++)
            #pragma unroll
            for (int j = 0; j < 4; j++) acc[mi][ni][j] = 0.0f;

    auto load_tile = [&](int stg, int kt) {
        const uint32_t dA = sbase + stg * (STG_FLOATS * 4);
        const uint32_t dB = dA + BM * SROW * 4;
        const int kofs = kt * BKF;
        #pragma unroll
        for (int i = 0; i < 4; i++) {
            int chunk = tid + i * 256;
            int r = chunk >> 3, c = chunk & 7;
            cp16(dA + (r * SROW + c * 4) * 4, Ag + (size_t)r * K + kofs + c * 4);
            cp16(dB + (r * SROW + c * 4) * 4, Wg + (size_t)r * K + kofs + c * 4);
        }
    };

    const int nk = K / BKF;
    load_tile(0, 0);
    CP_COMMIT;

    for (int kt = 0; kt < nk; kt++) {
        const int buf = kt & 1;
        if (kt + 1 < nk) load_tile(buf ^ 1, kt + 1);
        CP_COMMIT;
        CP_WAIT1;
        __syncthreads();

        const float* As = sm + buf * STG_FLOATS;
        const float* Bs = As + BM * SROW;
        const float* aB = As + (wm + g) * SROW + t;
        const float* bB = Bs + (wn + g) * SROW + t;

        #pragma unroll
        for (int ks = 0; ks < 4; ks++) {
            const int k0 = ks * 8;
            uint32_t af[2][4];
            #pragma unroll
            for (int mi = 0; mi < 2; mi++) {
                const float* p = aB + mi * 16 * SROW + k0;
                af[mi][0] = __float_as_uint(p[0]);
                af[mi][1] = __float_as_uint(p[8 * SROW]);
                af[mi][2] = __float_as_uint(p[4]);
                af[mi][3] = __float_as_uint(p[8 * SROW + 4]);
            }
            #pragma unroll
            for (int ni = 0; ni < 8; ni++) {
                const float* p = bB + ni * 8 * SROW + k0;
                uint32_t b0 = __float_as_uint(p[0]);
                uint32_t b1 = __float_as_uint(p[4]);
                mma8(acc[0][ni], af[0], b0, b1);
                mma8(acc[1][ni], af[1], b0, b1);
            }
        }
        __syncthreads();
    }

    // epilogue
    float bb[8][2];
    #pragma unroll
    for (int ni = 0; ni < 8; ni++) {
        int col = bn + wn + ni * 8 + t * 2;
        bb[ni][0] = __ldg(bias + col);
        bb[ni][1] = __ldg(bias + col + 1);
    }
    #pragma unroll
    for (int mi = 0; mi < 2; mi++) {
        #pragma unroll
        for (int h = 0; h < 2; h++) {
            const int row = bm + wm + mi * 16 + g + h * 8;
            #pragma unroll
            for (int ni = 0; ni < 8; ni++) {
                const int col = bn + wn + ni * 8 + t * 2;
                float o0 = acc[mi][ni][h * 2 + 0] + bb[ni][0];
                float o1 = acc[mi][ni][h * 2 + 1] + bb[ni][1];
                if (EPI == 2) {
                    o0 = 0.5f * o0 * (1.0f + erff(o0 * 0.70710678118654752f));
                    o1 = 0.5f * o1 * (1.0f + erff(o1 * 0.70710678118654752f));
                }
                if (EPI == 0 || EPI == 2) { o0 = rtf32(o0); o1 = rtf32(o1); }
                if (EPI == 1) {
                    const float2 rv = *(const float2*)(res + (size_t)row * N + col);
                    o0 += rv.x; o1 += rv.y;
                }
                *(float2*)(C + (size_t)row * N + col) = make_float2(o0, o1);
            }
        }
    }
}

// ---------------------------------------------------------------------------
// LayerNorm: one block per token row of 1024; output rounded to tf32
// ---------------------------------------------------------------------------
__global__ void __launch_bounds__(256) ln_kernel(const float* __restrict__ x,
                                                 const float* __restrict__ g,
                                                 const float* __restrict__ b,
                                                 float* __restrict__ out) {
    int row = blockIdx.x;
    const float4* xr = (const float4*)(x + (size_t)row * EE);
    float4 v = xr[threadIdx.x];
    float s  = v.x + v.y + v.z + v.w;
    float sq = v.x * v.x + v.y * v.y + v.z * v.z + v.w * v.w;
    #pragma unroll
    for (int o = 16; o; o >>= 1) {
        s  += __shfl_xor_sync(0xffffffffu, s,  o);
        sq += __shfl_xor_sync(0xffffffffu, sq, o);
    }
    __shared__ float ss[8], ssq[8];
    int w = threadIdx.x >> 5, ln = threadIdx.x & 31;
    if (ln == 0) { ss[w] = s; ssq[w] = sq; }
    __syncthreads();
    if (w == 0) {
        s  = (ln < 8) ? ss[ln]  : 0.0f;
        sq = (ln < 8) ? ssq[ln] : 0.0f;
        #pragma unroll
        for (int o = 4; o; o >>= 1) {
            s  += __shfl_xor_sync(0xffffffffu, s,  o);
            sq += __shfl_xor_sync(0xffffffffu, sq, o);
        }
        if (ln == 0) { ss[0] = s; ssq[0] = sq; }
    }
    __syncthreads();
    float mean = ss[0] * (1.0f / EE);
    float var  = ssq[0] * (1.0f / EE) - mean * mean;
    float rstd = rsqrtf(var + 1e-5f);
    int c = threadIdx.x * 4;
    float4 gg = *(const float4*)(g + c);
    float4 bb = *(const float4*)(b + c);
    float4 o4;
    o4.x = rtf32((v.x - mean) * rstd * gg.x + bb.x);
    o4.y = rtf32((v.y - mean) * rstd * gg.y + bb.y);
    o4.z = rtf32((v.z - mean) * rstd * gg.z + bb.z);
    o4.w = rtf32((v.w - mean) * rstd * gg.w + bb.w);
    ((float4*)(out + (size_t)row * EE))[threadIdx.x] = o4;
}

// ---------------------------------------------------------------------------
// Tensor-core flash attention, custom mask (j > i) || (j % TD == TD-1).
// 128-query CTA tile, 64-kv chunks, 8 warps x 16 q-rows, mma.sync tf32.
// Q/K/V already tf32-rounded by QKV GEMM epilogue.
// ---------------------------------------------------------------------------
#define AST 68   // smem row stride (floats): (4g+t) conflict-free fragment loads
#define ATT_SMEM ((128 * AST + 64 * AST + 64 * AST + 128 * AST) * 4)

__global__ void __launch_bounds__(256, 2) attn_tc(const float* __restrict__ qkv,
                                                  const int* __restrict__ tdp,
                                                  float* __restrict__ out) {
    extern __shared__ float sm[];
    float* Qs = sm;                    // [128][AST]
    float* Ks = Qs + 128 * AST;        // [64][AST]
    float* Vs = Ks + 64 * AST;         // [64][AST]
    float* Ps = Vs + 64 * AST;         // [128][AST]

    const int qb = blockIdx.x, bh = blockIdx.y;
    const int b = bh >> 4, h = bh & 15;
    const int TD = tdp[0];
    const int tid = threadIdx.x, w = tid >> 5, lane = tid & 31;
    const int g = lane >> 2, t = lane & 3;

    const size_t base = (size_t)b * SS * E3 + (size_t)h * DH;

    // load Q tile 128x64
    for (int i = tid; i < 128 * 16; i += 256) {
        int r = i >> 4, c = (i & 15) * 4;
        float4 v = *(const float4*)(qkv + base + (size_t)(qb * 128 + r) * E3 + c);
        float* d = Qs + r * AST + c;
        d[0] = v.x; d[1] = v.y; d[2] = v.z; d[3] = v.w;
    }

    float m0 = -1e30f, m1 = -1e30f, l0 = 0.0f, l1 = 0.0f;
    float o[8][4];
    #pragma unroll
    for (int ni = 0; ni < 8; ni++)
        #pragma unroll
        for (int j = 0; j < 4; j++) o[ni][j] = 0.0f;

    const int ig0 = qb * 128 + w * 16 + g;
    const int ig1 = ig0 + 8;
    const int nkt = 2 * qb + 2;

    for (int kb = 0; kb < nkt; kb++) {
        __syncthreads();
        for (int i = tid; i < 64 * 16; i += 256) {
            int r = i >> 4, c = (i & 15) * 4;
            size_t off = base + (size_t)(kb * 64 + r) * E3 + c;
            float4 kv4 = *(const float4*)(qkv + off + EE);
            float4 vv4 = *(const float4*)(qkv + off + 2 * EE);
            float* dk = Ks + r * AST + c;
            float* dv = Vs + r * AST + c;
            dk[0] = kv4.x; dk[1] = kv4.y; dk[2] = kv4.z; dk[3] = kv4.w;
            dv[0] = vv4.x; dv[1] = vv4.y; dv[2] = vv4.z; dv[3] = vv4.w;
        }
        __syncthreads();

        // --- scores = Q @ K^T ---
        float s[8][4];
        #pragma unroll
        for (int ni = 0; ni < 8; ni++)
            #pragma unroll
            for (int j = 0; j < 4; j++) s[ni][j] = 0.0f;

        const float* aQ = Qs + (w * 16 + g) * AST + t;
        const float* bK = Ks + g * AST + t;
        #pragma unroll
        for (int ks = 0; ks < 8; ks++) {
            const int k0 = ks * 8;
            uint32_t a[4];
            a[0] = __float_as_uint(aQ[k0]);
            a[1] = __float_as_uint(aQ[8 * AST + k0]);
            a[2] = __float_as_uint(aQ[k0 + 4]);
            a[3] = __float_as_uint(aQ[8 * AST + k0 + 4]);
            #pragma unroll
            for (int ni = 0; ni < 8; ni++) {
                uint32_t b0 = __float_as_uint(bK[ni * 8 * AST + k0]);
                uint32_t b1 = __float_as_uint(bK[ni * 8 * AST + k0 + 4]);
                mma8(s[ni], a, b0, b1);
            }
        }

        // --- mask + scale + online softmax ---
        float rm0 = -1e30f, rm1 = -1e30f;
        #pragma unroll
        for (int ni = 0; ni < 8; ni++) {
            #pragma unroll
            for (int j = 0; j < 2; j++) {
                const int col = kb * 64 + ni * 8 + t * 2 + j;
                const bool dead = ((col % TD) == TD - 1);
                float v0 = (dead || col > ig0) ? -1e30f : s[ni][j] * 0.125f;
                float v1 = (dead || col > ig1) ? -1e30f : s[ni][2 + j] * 0.125f;
                s[ni][j] = v0; s[ni][2 + j] = v1;
                rm0 = fmaxf(rm0, v0); rm1 = fmaxf(rm1, v1);
            }
        }
        #pragma unroll
        for (int ofs = 1; ofs < 4; ofs <<= 1) {
            rm0 = fmaxf(rm0, __shfl_xor_sync(0xffffffffu, rm0, ofs));
            rm1 = fmaxf(rm1, __shfl_xor_sync(0xffffffffu, rm1, ofs));
        }
        const float nm0 = fmaxf(m0, rm0), nm1 = fmaxf(m1, rm1);
        const float a0 = __expf(m0 - nm0), a1 = __expf(m1 - nm1);
        m0 = nm0; m1 = nm1;

        float rs0 = 0.0f, rs1 = 0.0f;
        float* pR0 = Ps + (w * 16 + g) * AST;
        float* pR1 = pR0 + 8 * AST;
        #pragma unroll
        for (int ni = 0; ni < 8; ni++) {
            float p00 = __expf(s[ni][0] - m0), p01 = __expf(s[ni][1] - m0);
            float p10 = __expf(s[ni][2] - m1), p11 = __expf(s[ni][3] - m1);
            rs0 += p00 + p01; rs1 += p10 + p11;
            const int c = ni * 8 + t * 2;
            *(float2*)(pR0 + c) = make_float2(rtf32(p00), rtf32(p01));
            *(float2*)(pR1 + c) = make_float2(rtf32(p10), rtf32(p11));
        }
        #pragma unroll
        for (int ofs = 1; ofs < 4; ofs <<= 1) {
            rs0 += __shfl_xor_sync(0xffffffffu, rs0, ofs);
            rs1 += __shfl_xor_sync(0xffffffffu, rs1, ofs);
        }
        l0 = l0 * a0 + rs0;
        l1 = l1 * a1 + rs1;
        #pragma unroll
        for (int ni = 0; ni < 8; ni++) {
            o[ni][0] *= a0; o[ni][1] *= a0;
            o[ni][2] *= a1; o[ni][3] *= a1;
        }
        __syncwarp();

        // --- O += P @ V ---
        const float* aP = Ps + (w * 16 + g) * AST + t;
        #pragma unroll
        for (int ks = 0; ks < 8; ks++) {
            const int k0 = ks * 8;
            uint32_t a[4];
            a[0] = __float_as_uint(aP[k0]);
            a[1] = __float_as_uint(aP[8 * AST + k0]);
            a[2] = __float_as_uint(aP[k0 + 4]);
            a[3] = __float_as_uint(aP[8 * AST + k0 + 4]);
            #pragma unroll
            for (int ni = 0; ni < 8; ni++) {
                uint32_t b0 = __float_as_uint(Vs[(k0 + t) * AST + ni * 8 + g]);
                uint32_t b1 = __float_as_uint(Vs[(k0 + t + 4) * AST + ni * 8 + g]);
                mma8(o[ni], a, b0, b1);
            }
        }
    }

    // epilogue (rounded: feeds O-projection mma)
    const float inv0 = 1.0f / l0, inv1 = 1.0f / l1;
    const size_t r0o = ((size_t)(b * SS + qb * 128 + w * 16 + g)) * EE + h * DH;
    const size_t r1o = r0o + 8 * EE;
    #pragma unroll
    for (int ni = 0; ni < 8; ni++) {
        const int c = ni * 8 + t * 2;
        *(float2*)(out + r0o + c) =
            make_float2(rtf32(o[ni][0] * inv0), rtf32(o[ni][1] * inv0));
        *(float2*)(out + r1o + c) =
            make_float2(rtf32(o[ni][2] * inv1), rtf32(o[ni][3] * inv1));
    }
}

// ---------------------------------------------------------------------------
// Launch
// ---------------------------------------------------------------------------
extern "C" void kernel_launch(void* const* d_in, const int* in_sizes, int n_in,
                              void* d_out, int out_size) {
    const float* x      = (const float*)d_in[0];
    const int*   td     = (const int*)d_in[1];
    const float* ln1_g  = (const float*)d_in[2];
    const float* ln1_b  = (const float*)d_in[3];
    const float* ln2_g  = (const float*)d_in[4];
    const float* ln2_b  = (const float*)d_in[5];
    const float* w_qkv  = (const float*)d_in[6];
    const float* b_qkv  = (const float*)d_in[7];
    const float* w_o    = (const float*)d_in[8];
    const float* b_o    = (const float*)d_in[9];
    const float* w_fc1  = (const float*)d_in[10];
    const float* b_fc1  = (const float*)d_in[11];
    const float* w_fc2  = (const float*)d_in[12];
    const float* b_fc2  = (const float*)d_in[13];
    float* out = (float*)d_out;

    float *xn, *qkvb, *attnb, *x2, *fc1b, *wc;
    cudaGetSymbolAddress((void**)&xn,    g_xn);
    cudaGetSymbolAddress((void**)&qkvb,  g_qkv);
    cudaGetSymbolAddress((void**)&attnb, g_attn);
    cudaGetSymbolAddress((void**)&x2,    g_x2);
    cudaGetSymbolAddress((void**)&fc1b,  g_fc1);
    cudaGetSymbolAddress((void**)&wc,    g_wc);

    float* wc_qkv = wc;
    float* wc_o   = wc + (size_t)3 * 1024 * 1024;
    float* wc_fc1 = wc + (size_t)4 * 1024 * 1024;
    float* wc_fc2 = wc + (size_t)8 * 1024 * 1024;

    const int dsm = 2 * STG_FLOATS * 4;  // 73728 bytes
    cudaFuncSetAttribute(gemm_mma<0>, cudaFuncAttributeMaxDynamicSharedMemorySize, dsm);
    cudaFuncSetAttribute(gemm_mma<1>, cudaFuncAttributeMaxDynamicSharedMemorySize, dsm);
    cudaFuncSetAttribute(gemm_mma<2>, cudaFuncAttributeMaxDynamicSharedMemorySize, dsm);
    cudaFuncSetAttribute(attn_tc, cudaFuncAttributeMaxDynamicSharedMemorySize, ATT_SMEM);

    // 0. Round weights to tf32 once per call
    round_kernel<<<(E3 * EE / 4 + 255) / 256, 256>>>(w_qkv, wc_qkv, E3 * EE);
    round_kernel<<<(EE * EE / 4 + 255) / 256, 256>>>(w_o,   wc_o,   EE * EE);
    round_kernel<<<(FFD * EE / 4 + 255) / 256, 256>>>(w_fc1, wc_fc1, FFD * EE);
    round_kernel<<<(EE * FFD / 4 + 255) / 256, 256>>>(w_fc2, wc_fc2, EE * FFD);

    // 1. LN1 (tf32-rounded output)
    ln_kernel<<<MM, 256>>>(x, ln1_g, ln1_b, xn);
    // 2. QKV projection (tf32-rounded output)
    gemm_mma<0><<<dim3(E3 / BN, MM / BM), 256, dsm>>>(xn, wc_qkv, b_qkv, nullptr,
                                                      qkvb, MM, E3, EE);
    // 3. Tensor-core attention
    attn_tc<<<dim3(SS / 128, BB * HH), 256, ATT_SMEM>>>(qkvb, td, attnb);
    // 4. O projection + residual
    gemm_mma<1><<<dim3(EE / BN, MM / BM), 256, dsm>>>(attnb, wc_o, b_o, x,
                                                      x2, MM, EE, EE);
    // 5. LN2
    ln_kernel<<<MM, 256>>>(x2, ln2_g, ln2_b, xn);
    // 6. FC1 + GELU (tf32-rounded output)
    gemm_mma<2><<<dim3(FFD / BN, MM / BM), 256, dsm>>>(xn, wc_fc1, b_fc1, nullptr,
                                                       fc1b, MM, FFD, EE);
    // 7. FC2 + residual -> out
    gemm_mma<1><<<dim3(EE / BN, MM / BM), 256, dsm>>>(fc1b, wc_fc2, b_fc2, x2,
                                                      out, MM, EE, FFD);
}

// round 5
// speedup vs baseline: 3.4229x; 1.1250x over previous
#include <cuda_runtime.h>
#include <math.h>
#include <stdint.h>

// Problem constants
#define BB 4
#define SS 2048
#define EE 1024
#define HH 16
#define DH 64
#define FFD 4096
#define MM (BB * SS)          // 8192 tokens
#define E3 (3 * EE)           // 3072

// ---------------------------------------------------------------------------
// Scratch buffers (device globals; allocation-free)
// ---------------------------------------------------------------------------
__device__ __align__(128) float g_xn[(size_t)MM * EE];
__device__ __align__(128) float g_qkv[(size_t)MM * E3];
__device__ __align__(128) float g_attn[(size_t)MM * EE];
__device__ __align__(128) float g_x2[(size_t)MM * EE];
__device__ __align__(128) float g_fc1[(size_t)MM * FFD];
// tf32-rounded weights: qkv(3M) | o(1M) | fc1(4M) | fc2(4M)
__device__ __align__(128) float g_wc[(size_t)12 * 1024 * 1024];

// ---------------------------------------------------------------------------
// Helpers
// ---------------------------------------------------------------------------
__device__ __forceinline__ float rtf32(float x) {
    uint32_t u;
    asm("cvt.rna.tf32.f32 %0, %1;" : "=r"(u) : "f"(x));
    return __uint_as_float(u);
}
__device__ __forceinline__ uint32_t smem_u32(const void* p) {
    uint32_t a;
    asm("{ .reg .u64 t; cvta.to.shared.u64 t, %1; cvt.u32.u64 %0, t; }"
        : "=r"(a) : "l"(p));
    return a;
}
__device__ __forceinline__ void cp16(uint32_t s, const void* g) {
    asm volatile("cp.async.cg.shared.global [%0], [%1], 16;" :: "r"(s), "l"(g));
}
#define CP_COMMIT asm volatile("cp.async.commit_group;" ::: "memory")
#define CP_WAIT1  asm volatile("cp.async.wait_group 1;" ::: "memory")

__device__ __forceinline__ void mma8(float c[4], const uint32_t a[4],
                                     uint32_t b0, uint32_t b1) {
    asm volatile(
        "mma.sync.aligned.m16n8k8.row.col.f32.tf32.tf32.f32 "
        "{%0,%1,%2,%3}, {%4,%5,%6,%7}, {%8,%9}, {%0,%1,%2,%3};"
        : "+f"(c[0]), "+f"(c[1]), "+f"(c[2]), "+f"(c[3])
        : "r"(a[0]), "r"(a[1]), "r"(a[2]), "r"(a[3]), "r"(b0), "r"(b1));
}
// ldmatrix x4: four 8x8xb16 matrices == four 8x4xtf32 fragments
#define LDSM4(r, addr) \
    asm volatile("ldmatrix.sync.aligned.m8n8.x4.shared.b16 {%0,%1,%2,%3}, [%4];" \
        : "=r"((r)[0]), "=r"((r)[1]), "=r"((r)[2]), "=r"((r)[3]) : "r"(addr))

// ---------------------------------------------------------------------------
// Weight round-to-tf32 pass
// ---------------------------------------------------------------------------
__global__ void __launch_bounds__(256) round_kernel(const float* __restrict__ in,
                                                    float* __restrict__ out, int n) {
    int i = (blockIdx.x * 256 + threadIdx.x) * 4;
    if (i < n) {
        float4 v = *(const float4*)(in + i);
        v.x = rtf32(v.x); v.y = rtf32(v.y); v.z = rtf32(v.z); v.w = rtf32(v.w);
        *(float4*)(out + i) = v;
    }
}

// ---------------------------------------------------------------------------
// TF32 mma.sync GEMM NT with ldmatrix fragment loads.
//   EPI 0: + bias, round to tf32   EPI 1: + bias + residual
//   EPI 2: + bias, exact GELU, round to tf32
// CTA 128x128x32, 8 warps (4Mx2N), warp tile 32x64, double-buffered cp.async.
// ---------------------------------------------------------------------------
#define BM 128
#define BN 128
#define BKF 32
#define SROW 36                      // padded smem row stride (floats)
#define STG_FLOATS (2 * BM * SROW)   // As+Bs per stage
#define STGB (STG_FLOATS * 4)

template <int EPI>
__global__ void __launch_bounds__(256, 2) gemm_mma(
    const float* __restrict__ A, const float* __restrict__ W,
    const float* __restrict__ bias, const float* __restrict__ res,
    float* __restrict__ C, int M, int N, int K)
{
    extern __shared__ float sm[];
    const int tid = threadIdx.x;
    const int bm = blockIdx.y * BM;
    const int bn = blockIdx.x * BN;
    const uint32_t sbase = smem_u32(sm);

    const int w = tid >> 5, lane = tid & 31;
    const int t = lane & 3;
    const int g = lane >> 2;
    const int wm = (w & 3) * 32;
    const int wn = (w >> 2) * 64;

    // ldmatrix source offsets (bytes, within stage)
    const uint32_t aLd = ((wm + (lane & 15)) * SROW + ((lane >> 4) << 2)) * 4;
    const uint32_t bLd = ((wn + (lane & 7) + ((lane >> 4) << 3)) * SROW
                          + (((lane >> 3) & 1) << 2)) * 4;

    const float* Ag = A + (size_t)bm * K;
    const float* Wg = W + (size_t)bn * K;

    float acc[2][8][4];
    #pragma unroll
    for (int mi = 0; mi < 2; mi++)
        #pragma unroll
        for (int ni = 0; ni < 8; ni++)
            #pragma unroll
            for (int j = 0; j < 4; j++) acc[mi][ni][j] = 0.0f;

    auto load_tile = [&](int stg, int kt) {
        const uint32_t dA = sbase + stg * STGB;
        const uint32_t dB = dA + BM * SROW * 4;
        const int kofs = kt * BKF;
        #pragma unroll
        for (int i = 0; i < 4; i++) {
            int chunk = tid + i * 256;
            int r = chunk >> 3, c = chunk & 7;
            cp16(dA + (r * SROW + c * 4) * 4, Ag + (size_t)r * K + kofs + c * 4);
            cp16(dB + (r * SROW + c * 4) * 4, Wg + (size_t)r * K + kofs + c * 4);
        }
    };

    const int nk = K / BKF;
    load_tile(0, 0);
    CP_COMMIT;

    for (int kt = 0; kt < nk; kt++) {
        const int buf = kt & 1;
        if (kt + 1 < nk) load_tile(buf ^ 1, kt + 1);
        CP_COMMIT;
        CP_WAIT1;
        __syncthreads();

        const uint32_t aBase = sbase + buf * STGB + aLd;
        const uint32_t bBase = sbase + buf * STGB + BM * SROW * 4 + bLd;

        #pragma unroll
        for (int ks = 0; ks < 4; ks++) {
            const uint32_t ko = ks * 32;   // 8 floats
            uint32_t a0[4], a1[4], bq[4][4];
            LDSM4(a0, aBase + ko);
            LDSM4(a1, aBase + 16 * SROW * 4 + ko);
            #pragma unroll
            for (int p = 0; p < 4; p++)
                LDSM4(bq[p], bBase + p * 16 * SROW * 4 + ko);
            #pragma unroll
            for (int p = 0; p < 4; p++) {
                mma8(acc[0][2 * p],     a0, bq[p][0], bq[p][1]);
                mma8(acc[0][2 * p + 1], a0, bq[p][2], bq[p][3]);
                mma8(acc[1][2 * p],     a1, bq[p][0], bq[p][1]);
                mma8(acc[1][2 * p + 1], a1, bq[p][2], bq[p][3]);
            }
        }
        __syncthreads();
    }

    // epilogue
    float bb[8][2];
    #pragma unroll
    for (int ni = 0; ni < 8; ni++) {
        int col = bn + wn + ni * 8 + t * 2;
        bb[ni][0] = __ldg(bias + col);
        bb[ni][1] = __ldg(bias + col + 1);
    }
    #pragma unroll
    for (int mi = 0; mi < 2; mi++) {
        #pragma unroll
        for (int h = 0; h < 2; h++) {
            const int row = bm + wm + mi * 16 + g + h * 8;
            #pragma unroll
            for (int ni = 0; ni < 8; ni++) {
                const int col = bn + wn + ni * 8 + t * 2;
                float o0 = acc[mi][ni][h * 2 + 0] + bb[ni][0];
                float o1 = acc[mi][ni][h * 2 + 1] + bb[ni][1];
                if (EPI == 2) {
                    o0 = 0.5f * o0 * (1.0f + erff(o0 * 0.70710678118654752f));
                    o1 = 0.5f * o1 * (1.0f + erff(o1 * 0.70710678118654752f));
                }
                if (EPI == 0 || EPI == 2) { o0 = rtf32(o0); o1 = rtf32(o1); }
                if (EPI == 1) {
                    const float2 rv = *(const float2*)(res + (size_t)row * N + col);
                    o0 += rv.x; o1 += rv.y;
                }
                *(float2*)(C + (size_t)row * N + col) = make_float2(o0, o1);
            }
        }
    }
}

// ---------------------------------------------------------------------------
// LayerNorm: one block per token row of 1024; output rounded to tf32
// ---------------------------------------------------------------------------
__global__ void __launch_bounds__(256) ln_kernel(const float* __restrict__ x,
                                                 const float* __restrict__ g,
                                                 const float* __restrict__ b,
                                                 float* __restrict__ out) {
    int row = blockIdx.x;
    const float4* xr = (const float4*)(x + (size_t)row * EE);
    float4 v = xr[threadIdx.x];
    float s  = v.x + v.y + v.z + v.w;
    float sq = v.x * v.x + v.y * v.y + v.z * v.z + v.w * v.w;
    #pragma unroll
    for (int o = 16; o; o >>= 1) {
        s  += __shfl_xor_sync(0xffffffffu, s,  o);
        sq += __shfl_xor_sync(0xffffffffu, sq, o);
    }
    __shared__ float ss[8], ssq[8];
    int w = threadIdx.x >> 5, ln = threadIdx.x & 31;
    if (ln == 0) { ss[w] = s; ssq[w] = sq; }
    __syncthreads();
    if (w == 0) {
        s  = (ln < 8) ? ss[ln]  : 0.0f;
        sq = (ln < 8) ? ssq[ln] : 0.0f;
        #pragma unroll
        for (int o = 4; o; o >>= 1) {
            s  += __shfl_xor_sync(0xffffffffu, s,  o);
            sq += __shfl_xor_sync(0xffffffffu, sq, o);
        }
        if (ln == 0) { ss[0] = s; ssq[0] = sq; }
    }
    __syncthreads();
    float mean = ss[0] * (1.0f / EE);
    float var  = ssq[0] * (1.0f / EE) - mean * mean;
    float rstd = rsqrtf(var + 1e-5f);
    int c = threadIdx.x * 4;
    float4 gg = *(const float4*)(g + c);
    float4 bb = *(const float4*)(b + c);
    float4 o4;
    o4.x = rtf32((v.x - mean) * rstd * gg.x + bb.x);
    o4.y = rtf32((v.y - mean) * rstd * gg.y + bb.y);
    o4.z = rtf32((v.z - mean) * rstd * gg.z + bb.z);
    o4.w = rtf32((v.w - mean) * rstd * gg.w + bb.w);
    ((float4*)(out + (size_t)row * EE))[threadIdx.x] = o4;
}

// ---------------------------------------------------------------------------
// Tensor-core flash attention, custom mask (j > i) || (j % TD == TD-1).
// 128-query CTA tile, 64-kv chunks, 8 warps x 16 q-rows, mma.sync + ldmatrix.
// ---------------------------------------------------------------------------
#define AST 68
#define ATT_SMEM ((128 * AST + 64 * AST + 64 * AST + 128 * AST) * 4)

__global__ void __launch_bounds__(256, 2) attn_tc(const float* __restrict__ qkv,
                                                  const int* __restrict__ tdp,
                                                  float* __restrict__ out) {
    extern __shared__ float sm[];
    float* Qs = sm;                    // [128][AST]
    float* Ks = Qs + 128 * AST;        // [64][AST]
    float* Vs = Ks + 64 * AST;         // [64][AST]
    float* Ps = Vs + 64 * AST;         // [128][AST]

    const int qb = blockIdx.x, bh = blockIdx.y;
    const int b = bh >> 4, h = bh & 15;
    const int TD = tdp[0];
    const int tid = threadIdx.x, w = tid >> 5, lane = tid & 31;
    const int g = lane >> 2, t = lane & 3;

    const size_t base = (size_t)b * SS * E3 + (size_t)h * DH;

    // ldmatrix offsets (bytes)
    const uint32_t qLd = smem_u32(Qs) +
        ((w * 16 + (lane & 15)) * AST + ((lane >> 4) << 2)) * 4;
    const uint32_t kLd = smem_u32(Ks) +
        (((lane & 7) + ((lane >> 4) << 3)) * AST + (((lane >> 3) & 1) << 2)) * 4;
    const uint32_t pLd = smem_u32(Ps) +
        ((w * 16 + (lane & 15)) * AST + ((lane >> 4) << 2)) * 4;

    // load Q tile 128x64
    for (int i = tid; i < 128 * 16; i += 256) {
        int r = i >> 4, c = (i & 15) * 4;
        float4 v = *(const float4*)(qkv + base + (size_t)(qb * 128 + r) * E3 + c);
        float* d = Qs + r * AST + c;
        d[0] = v.x; d[1] = v.y; d[2] = v.z; d[3] = v.w;
    }

    float m0 = -1e30f, m1 = -1e30f, l0 = 0.0f, l1 = 0.0f;
    float o[8][4];
    #pragma unroll
    for (int ni = 0; ni < 8; ni++)
        #pragma unroll
        for (int j = 0; j < 4; j++) o[ni][j] = 0.0f;

    const int ig0 = qb * 128 + w * 16 + g;
    const int ig1 = ig0 + 8;
    const int nkt = 2 * qb + 2;

    for (int kb = 0; kb < nkt; kb++) {
        __syncthreads();
        for (int i = tid; i < 64 * 16; i += 256) {
            int r = i >> 4, c = (i & 15) * 4;
            size_t off = base + (size_t)(kb * 64 + r) * E3 + c;
            float4 kv4 = *(const float4*)(qkv + off + EE);
            float4 vv4 = *(const float4*)(qkv + off + 2 * EE);
            float* dk = Ks + r * AST + c;
            float* dv = Vs + r * AST + c;
            dk[0] = kv4.x; dk[1] = kv4.y; dk[2] = kv4.z; dk[3] = kv4.w;
            dv[0] = vv4.x; dv[1] = vv4.y; dv[2] = vv4.z; dv[3] = vv4.w;
        }
        __syncthreads();

        // --- scores = Q @ K^T (ldmatrix fragments) ---
        float s[8][4];
        #pragma unroll
        for (int ni = 0; ni < 8; ni++)
            #pragma unroll
            for (int j = 0; j < 4; j++) s[ni][j] = 0.0f;

        #pragma unroll
        for (int ks = 0; ks < 8; ks++) {
            const uint32_t ko = ks * 32;
            uint32_t aq[4];
            LDSM4(aq, qLd + ko);
            #pragma unroll
            for (int p = 0; p < 4; p++) {
                uint32_t bk[4];
                LDSM4(bk, kLd + p * 16 * AST * 4 + ko);
                mma8(s[2 * p],     aq, bk[0], bk[1]);
                mma8(s[2 * p + 1], aq, bk[2], bk[3]);
            }
        }

        // --- mask + scale + online softmax ---
        float rm0 = -1e30f, rm1 = -1e30f;
        #pragma unroll
        for (int ni = 0; ni < 8; ni++) {
            #pragma unroll
            for (int j = 0; j < 2; j++) {
                const int col = kb * 64 + ni * 8 + t * 2 + j;
                const bool dead = ((col % TD) == TD - 1);
                float v0 = (dead || col > ig0) ? -1e30f : s[ni][j] * 0.125f;
                float v1 = (dead || col > ig1) ? -1e30f : s[ni][2 + j] * 0.125f;
                s[ni][j] = v0; s[ni][2 + j] = v1;
                rm0 = fmaxf(rm0, v0); rm1 = fmaxf(rm1, v1);
            }
        }
        #pragma unroll
        for (int ofs = 1; ofs < 4; ofs <<= 1) {
            rm0 = fmaxf(rm0, __shfl_xor_sync(0xffffffffu, rm0, ofs));
            rm1 = fmaxf(rm1, __shfl_xor_sync(0xffffffffu, rm1, ofs));
        }
        const float nm0 = fmaxf(m0, rm0), nm1 = fmaxf(m1, rm1);
        const float a0 = __expf(m0 - nm0), a1 = __expf(m1 - nm1);
        m0 = nm0; m1 = nm1;

        float rs0 = 0.0f, rs1 = 0.0f;
        float* pR0 = Ps + (w * 16 + g) * AST;
        float* pR1 = pR0 + 8 * AST;
        #pragma unroll
        for (int ni = 0; ni < 8; ni++) {
            float p00 = __expf(s[ni][0] - m0), p01 = __expf(s[ni][1] - m0);
            float p10 = __expf(s[ni][2] - m1), p11 = __expf(s[ni][3] - m1);
            rs0 += p00 + p01; rs1 += p10 + p11;
            const int c = ni * 8 + t * 2;
            *(float2*)(pR0 + c) = make_float2(rtf32(p00), rtf32(p01));
            *(float2*)(pR1 + c) = make_float2(rtf32(p10), rtf32(p11));
        }
        #pragma unroll
        for (int ofs = 1; ofs < 4; ofs <<= 1) {
            rs0 += __shfl_xor_sync(0xffffffffu, rs0, ofs);
            rs1 += __shfl_xor_sync(0xffffffffu, rs1, ofs);
        }
        l0 = l0 * a0 + rs0;
        l1 = l1 * a1 + rs1;
        #pragma unroll
        for (int ni = 0; ni < 8; ni++) {
            o[ni][0] *= a0; o[ni][1] *= a0;
            o[ni][2] *= a1; o[ni][3] *= a1;
        }
        __syncwarp();

        // --- O += P @ V ---
        #pragma unroll
        for (int ks = 0; ks < 8; ks++) {
            const uint32_t ko = ks * 32;
            const int k0 = ks * 8;
            uint32_t a[4];
            LDSM4(a, pLd + ko);
            #pragma unroll
            for (int ni = 0; ni < 8; ni++) {
                uint32_t b0 = __float_as_uint(Vs[(k0 + t) * AST + ni * 8 + g]);
                uint32_t b1 = __float_as_uint(Vs[(k0 + t + 4) * AST + ni * 8 + g]);
                mma8(o[ni], a, b0, b1);
            }
        }
    }

    // epilogue (rounded: feeds O-projection mma)
    const float inv0 = 1.0f / l0, inv1 = 1.0f / l1;
    const size_t r0o = ((size_t)(b * SS + qb * 128 + w * 16 + g)) * EE + h * DH;
    const size_t r1o = r0o + 8 * EE;
    #pragma unroll
    for (int ni = 0; ni < 8; ni++) {
        const int c = ni * 8 + t * 2;
        *(float2*)(out + r0o + c) =
            make_float2(rtf32(o[ni][0] * inv0), rtf32(o[ni][1] * inv0));
        *(float2*)(out + r1o + c) =
            make_float2(rtf32(o[ni][2] * inv1), rtf32(o[ni][3] * inv1));
    }
}

// ---------------------------------------------------------------------------
// Launch
// ---------------------------------------------------------------------------
extern "C" void kernel_launch(void* const* d_in, const int* in_sizes, int n_in,
                              void* d_out, int out_size) {
    const float* x      = (const float*)d_in[0];
    const int*   td     = (const int*)d_in[1];
    const float* ln1_g  = (const float*)d_in[2];
    const float* ln1_b  = (const float*)d_in[3];
    const float* ln2_g  = (const float*)d_in[4];
    const float* ln2_b  = (const float*)d_in[5];
    const float* w_qkv  = (const float*)d_in[6];
    const float* b_qkv  = (const float*)d_in[7];
    const float* w_o    = (const float*)d_in[8];
    const float* b_o    = (const float*)d_in[9];
    const float* w_fc1  = (const float*)d_in[10];
    const float* b_fc1  = (const float*)d_in[11];
    const float* w_fc2  = (const float*)d_in[12];
    const float* b_fc2  = (const float*)d_in[13];
    float* out = (float*)d_out;

    float *xn, *qkvb, *attnb, *x2, *fc1b, *wc;
    cudaGetSymbolAddress((void**)&xn,    g_xn);
    cudaGetSymbolAddress((void**)&qkvb,  g_qkv);
    cudaGetSymbolAddress((void**)&attnb, g_attn);
    cudaGetSymbolAddress((void**)&x2,    g_x2);
    cudaGetSymbolAddress((void**)&fc1b,  g_fc1);
    cudaGetSymbolAddress((void**)&wc,    g_wc);

    float* wc_qkv = wc;
    float* wc_o   = wc + (size_t)3 * 1024 * 1024;
    float* wc_fc1 = wc + (size_t)4 * 1024 * 1024;
    float* wc_fc2 = wc + (size_t)8 * 1024 * 1024;

    const int dsm = 2 * STGB;  // 73728 bytes
    cudaFuncSetAttribute(gemm_mma<0>, cudaFuncAttributeMaxDynamicSharedMemorySize, dsm);
    cudaFuncSetAttribute(gemm_mma<1>, cudaFuncAttributeMaxDynamicSharedMemorySize, dsm);
    cudaFuncSetAttribute(gemm_mma<2>, cudaFuncAttributeMaxDynamicSharedMemorySize, dsm);
    cudaFuncSetAttribute(attn_tc, cudaFuncAttributeMaxDynamicSharedMemorySize, ATT_SMEM);

    // 0. Round weights to tf32 once per call
    round_kernel<<<(E3 * EE / 4 + 255) / 256, 256>>>(w_qkv, wc_qkv, E3 * EE);
    round_kernel<<<(EE * EE / 4 + 255) / 256, 256>>>(w_o,   wc_o,   EE * EE);
    round_kernel<<<(FFD * EE / 4 + 255) / 256, 256>>>(w_fc1, wc_fc1, FFD * EE);
    round_kernel<<<(EE * FFD / 4 + 255) / 256, 256>>>(w_fc2, wc_fc2, EE * FFD);

    // 1. LN1 (tf32-rounded output)
    ln_kernel<<<MM, 256>>>(x, ln1_g, ln1_b, xn);
    // 2. QKV projection (tf32-rounded output)
    gemm_mma<0><<<dim3(E3 / BN, MM / BM), 256, dsm>>>(xn, wc_qkv, b_qkv, nullptr,
                                                      qkvb, MM, E3, EE);
    // 3. Tensor-core attention
    attn_tc<<<dim3(SS / 128, BB * HH), 256, ATT_SMEM>>>(qkvb, td, attnb);
    // 4. O projection + residual
    gemm_mma<1><<<dim3(EE / BN, MM / BM), 256, dsm>>>(attnb, wc_o, b_o, x,
                                                      x2, MM, EE, EE);
    // 5. LN2
    ln_kernel<<<MM, 256>>>(x2, ln2_g, ln2_b, xn);
    // 6. FC1 + GELU (tf32-rounded output)
    gemm_mma<2><<<dim3(FFD / BN, MM / BM), 256, dsm>>>(xn, wc_fc1, b_fc1, nullptr,
                                                       fc1b, MM, FFD, EE);
    // 7. FC2 + residual -> out
    gemm_mma<1><<<dim3(EE / BN, MM / BM), 256, dsm>>>(fc1b, wc_fc2, b_fc2, x2,
                                                      out, MM, EE, FFD);
}